// round 1
// baseline (speedup 1.0000x reference)
#include <cuda_runtime.h>
#include <math.h>
#include <float.h>

// Per-task precomputed gating tables: only 6 distinct taskIDs exist.
__device__ float g_clean[6 * 64];
__device__ float g_std[6 * 64];

// ---------------------------------------------------------------------------
// Kernel 1: per-task precompute (6 blocks x 64 threads). Tiny.
// Computes clean_logits[t][e] and noise_std[t][e] for t in [0,6), e in [0,64).
// Block 0 additionally zeroes the 64-float `load` tail of the output.
// ---------------------------------------------------------------------------
__global__ void precompute_kernel(
    const float* __restrict__ embed,   // (6, 32)
    const float* __restrict__ ekeys,   // (32, 32)
    const float* __restrict__ Wq,      // (32, 32)
    const float* __restrict__ bq,      // (32)
    const float* __restrict__ Wk,      // (32, 32)
    const float* __restrict__ bk,      // (32)
    const float* __restrict__ Wg,      // (64, 32)
    const float* __restrict__ bg,      // (64)
    const float* __restrict__ Wn,      // (64, 32)
    const float* __restrict__ bn,      // (64)
    float* __restrict__ load_out)      // (64) -> zero it
{
    const int t = blockIdx.x;
    const int tid = threadIdx.x;

    __shared__ float s_q[32];
    __shared__ float s_k[32][32];   // [expert s][feature i]
    __shared__ float s_attn[4][32];
    __shared__ float s_ew[32];

    if (t == 0 && tid < 64) load_out[tid] = 0.0f;

    // q = (embed[t] @ Wq^T + bq) * 1/sqrt(D), D = 8
    if (tid < 32) {
        float acc = bq[tid];
        #pragma unroll
        for (int j = 0; j < 32; j++)
            acc = fmaf(embed[t * 32 + j], Wq[tid * 32 + j], acc);
        s_q[tid] = acc * 0.35355339059327373f;  // 1/sqrt(8)
    }

    // k = expert_keys @ Wk^T + bk  (32x32 entries; 64 threads x 16 each)
    for (int p = tid; p < 1024; p += 64) {
        const int s = p >> 5, i = p & 31;
        float acc = bk[i];
        #pragma unroll
        for (int j = 0; j < 32; j++)
            acc = fmaf(ekeys[s * 32 + j], Wk[i * 32 + j], acc);
        s_k[s][i] = acc;
    }
    __syncthreads();

    // scores[h][s] = sum_d q[h*8+d] * k[s][h*8+d]
    if (tid < 32) {
        #pragma unroll
        for (int h = 0; h < 4; h++) {
            float acc = 0.0f;
            #pragma unroll
            for (int d = 0; d < 8; d++)
                acc = fmaf(s_q[h * 8 + d], s_k[tid][h * 8 + d], acc);
            s_attn[h][tid] = acc;
        }
    }
    __syncthreads();

    // softmax over s per head (4 serial threads; 32 elems each — negligible)
    if (tid < 4) {
        float m = -FLT_MAX;
        for (int s = 0; s < 32; s++) m = fmaxf(m, s_attn[tid][s]);
        float sum = 0.0f;
        for (int s = 0; s < 32; s++) {
            const float e = expf(s_attn[tid][s] - m);
            s_attn[tid][s] = e;
            sum += e;
        }
        const float inv = 1.0f / sum;
        for (int s = 0; s < 32; s++) s_attn[tid][s] *= inv;
    }
    __syncthreads();

    // attn_weights = mean over heads; expert_weight = softmax over 32
    if (tid == 0) {
        float aw[32];
        float m = -FLT_MAX;
        for (int s = 0; s < 32; s++) {
            const float v = 0.25f * (s_attn[0][s] + s_attn[1][s] +
                                     s_attn[2][s] + s_attn[3][s]);
            aw[s] = v;
            m = fmaxf(m, v);
        }
        float sum = 0.0f;
        for (int s = 0; s < 32; s++) {
            const float e = expf(aw[s] - m);
            aw[s] = e;
            sum += e;
        }
        const float inv = 1.0f / sum;
        for (int s = 0; s < 32; s++) s_ew[s] = aw[s] * inv;
    }
    __syncthreads();

    // clean_logits[e], noise_std[e]; one thread per expert e = tid (0..63)
    {
        float c = bg[tid];
        float nv = bn[tid];
        #pragma unroll
        for (int s = 0; s < 32; s++) {
            const float w = s_ew[s];
            c  = fmaf(w, Wg[tid * 32 + s], c);
            nv = fmaf(w, Wn[tid * 32 + s], nv);
        }
        g_clean[t * 64 + tid] = c;
        // softplus, numerically stable
        const float sp = (nv > 0.0f) ? (nv + log1pf(expf(-nv)))
                                     : log1pf(expf(nv));
        g_std[t * 64 + tid] = sp + 0.01f;
    }
}

// ---------------------------------------------------------------------------
// Kernel 2: per-token gating. One token per thread. HBM-bound:
//   read noise row (256B) + write gates row (256B) per token.
// ---------------------------------------------------------------------------
__global__ __launch_bounds__(256, 4) void gate_kernel(
    const int*   __restrict__ taskID,
    const float* __restrict__ noise,
    float*       __restrict__ gates,
    float*       __restrict__ loadv,
    int B)
{
    // Row stride 68 floats (pad 4) -> the <=6 distinct task rows occupy
    // disjoint bank quads for float4 LDS (68 mod 32 = 4).
    __shared__ __align__(16) float s_cl[6 * 68];
    __shared__ __align__(16) float s_st[6 * 68];
    __shared__ float s_load[64];

    const int tid = threadIdx.x;
    if (tid < 64) s_load[tid] = 0.0f;
    for (int i = tid; i < 6 * 64; i += 256) {
        const int t = i >> 6, j = i & 63;
        s_cl[t * 68 + j] = g_clean[i];
        s_st[t * 68 + j] = g_std[i];
    }
    __syncthreads();

    const long long b = (long long)blockIdx.x * 256 + tid;
    if (b < B) {
        const int t = taskID[b];
        const float4* nz = (const float4*)(noise + b * 64ll);
        const float* cl = s_cl + t * 68;
        const float* st = s_st + t * 68;

        float v0 = -FLT_MAX, v1 = -FLT_MAX;
        int i0 = 0, i1 = 0;

        #pragma unroll
        for (int q = 0; q < 16; q++) {
            const float4 n = nz[q];
            const float4 c = *(const float4*)(cl + q * 4);
            const float4 s = *(const float4*)(st + q * 4);
            float l;
            // jax.lax.top_k tie semantics: strict '>' keeps earliest index.
            l = fmaf(n.x, s.x, c.x);
            if (l > v0) { v1 = v0; i1 = i0; v0 = l; i0 = q * 4 + 0; }
            else if (l > v1) { v1 = l; i1 = q * 4 + 0; }
            l = fmaf(n.y, s.y, c.y);
            if (l > v0) { v1 = v0; i1 = i0; v0 = l; i0 = q * 4 + 1; }
            else if (l > v1) { v1 = l; i1 = q * 4 + 1; }
            l = fmaf(n.z, s.z, c.z);
            if (l > v0) { v1 = v0; i1 = i0; v0 = l; i0 = q * 4 + 2; }
            else if (l > v1) { v1 = l; i1 = q * 4 + 2; }
            l = fmaf(n.w, s.w, c.w);
            if (l > v0) { v1 = v0; i1 = i0; v0 = l; i0 = q * 4 + 3; }
            else if (l > v1) { v1 = l; i1 = q * 4 + 3; }
        }

        // softmax over the top-2 (v0 >= v1, so exponent <= 0: stable)
        const float e = expf(v1 - v0);
        const float g0 = 1.0f / (1.0f + e);
        const float g1 = e * g0;

        float4* out = (float4*)(gates + b * 64ll);
        #pragma unroll
        for (int q = 0; q < 16; q++) {
            const int base = q * 4;
            float4 o;
            o.x = (base + 0 == i0) ? g0 : ((base + 0 == i1) ? g1 : 0.0f);
            o.y = (base + 1 == i0) ? g0 : ((base + 1 == i1) ? g1 : 0.0f);
            o.z = (base + 2 == i0) ? g0 : ((base + 2 == i1) ? g1 : 0.0f);
            o.w = (base + 3 == i0) ? g0 : ((base + 3 == i1) ? g1 : 0.0f);
            out[q] = o;
        }

        atomicAdd(&s_load[i0], g0);
        atomicAdd(&s_load[i1], g1);
    }
    __syncthreads();
    if (tid < 64) atomicAdd(&loadv[tid], s_load[tid]);
}

// ---------------------------------------------------------------------------
// Launch
// ---------------------------------------------------------------------------
extern "C" void kernel_launch(void* const* d_in, const int* in_sizes, int n_in,
                              void* d_out, int out_size)
{
    const int*   taskID = (const int*)  d_in[0];
    const float* noise  = (const float*)d_in[1];
    const float* embed  = (const float*)d_in[2];
    const float* ekeys  = (const float*)d_in[3];
    const float* Wq     = (const float*)d_in[4];
    const float* bq     = (const float*)d_in[5];
    const float* Wk     = (const float*)d_in[6];
    const float* bk     = (const float*)d_in[7];
    const float* Wg     = (const float*)d_in[8];
    const float* bg     = (const float*)d_in[9];
    const float* Wn     = (const float*)d_in[10];
    const float* bn     = (const float*)d_in[11];

    const int B = in_sizes[0];
    float* gates = (float*)d_out;
    float* loadv = (float*)d_out + (out_size - 64);  // load tail

    precompute_kernel<<<6, 64>>>(embed, ekeys, Wq, bq, Wk, bk,
                                 Wg, bg, Wn, bn, loadv);

    const int blocks = (B + 255) / 256;
    gate_kernel<<<blocks, 256>>>(taskID, noise, gates, loadv, B);
}

// round 2
// speedup vs baseline: 1.4236x; 1.4236x over previous
#include <cuda_runtime.h>
#include <math.h>
#include <float.h>

// Per-task precomputed gating tables: only 6 distinct taskIDs exist.
__device__ float g_clean[6 * 64];
__device__ float g_std[6 * 64];

// ---------------------------------------------------------------------------
// Kernel 1: per-task precompute (6 blocks x 64 threads). Tiny.
// ---------------------------------------------------------------------------
__global__ void precompute_kernel(
    const float* __restrict__ embed,   // (6, 32)
    const float* __restrict__ ekeys,   // (32, 32)
    const float* __restrict__ Wq,      // (32, 32)
    const float* __restrict__ bq,      // (32)
    const float* __restrict__ Wk,      // (32, 32)
    const float* __restrict__ bk,      // (32)
    const float* __restrict__ Wg,      // (64, 32)
    const float* __restrict__ bg,      // (64)
    const float* __restrict__ Wn,      // (64, 32)
    const float* __restrict__ bn,      // (64)
    float* __restrict__ load_out)      // (64) -> zero it
{
    const int t = blockIdx.x;
    const int tid = threadIdx.x;

    __shared__ float s_q[32];
    __shared__ float s_k[32][32];   // [expert s][feature i]
    __shared__ float s_ew[32];

    if (t == 0 && tid < 64) load_out[tid] = 0.0f;

    // q = (embed[t] @ Wq^T + bq) * 1/sqrt(8)
    if (tid < 32) {
        float acc = bq[tid];
        #pragma unroll
        for (int j = 0; j < 32; j++)
            acc = fmaf(embed[t * 32 + j], Wq[tid * 32 + j], acc);
        s_q[tid] = acc * 0.35355339059327373f;
    }

    // k = expert_keys @ Wk^T + bk  (32x32 entries; 64 threads x 16 each)
    for (int p = tid; p < 1024; p += 64) {
        const int s = p >> 5, i = p & 31;
        float acc = bk[i];
        #pragma unroll
        for (int j = 0; j < 32; j++)
            acc = fmaf(ekeys[s * 32 + j], Wk[i * 32 + j], acc);
        s_k[s][i] = acc;
    }
    __syncthreads();

    // Warp 0 (lanes = experts s): scores, per-head softmax, mean, softmax.
    if (tid < 32) {
        float sc[4];
        #pragma unroll
        for (int h = 0; h < 4; h++) {
            float acc = 0.0f;
            #pragma unroll
            for (int d = 0; d < 8; d++)
                acc = fmaf(s_q[h * 8 + d], s_k[tid][h * 8 + d], acc);
            sc[h] = acc;
        }
        float aw = 0.0f;
        #pragma unroll
        for (int h = 0; h < 4; h++) {
            float m = sc[h];
            #pragma unroll
            for (int d = 16; d; d >>= 1)
                m = fmaxf(m, __shfl_xor_sync(0xffffffffu, m, d));
            float e = expf(sc[h] - m);
            float sum = e;
            #pragma unroll
            for (int d = 16; d; d >>= 1)
                sum += __shfl_xor_sync(0xffffffffu, sum, d);
            aw += 0.25f * (e / sum);
        }
        float m2 = aw;
        #pragma unroll
        for (int d = 16; d; d >>= 1)
            m2 = fmaxf(m2, __shfl_xor_sync(0xffffffffu, m2, d));
        float e2 = expf(aw - m2);
        float s2 = e2;
        #pragma unroll
        for (int d = 16; d; d >>= 1)
            s2 += __shfl_xor_sync(0xffffffffu, s2, d);
        s_ew[tid] = e2 / s2;
    }
    __syncthreads();

    // clean_logits[e], noise_std[e]; one thread per expert e = tid (0..63)
    {
        float c = bg[tid];
        float nv = bn[tid];
        #pragma unroll
        for (int s = 0; s < 32; s++) {
            const float w = s_ew[s];
            c  = fmaf(w, Wg[tid * 32 + s], c);
            nv = fmaf(w, Wn[tid * 32 + s], nv);
        }
        g_clean[t * 64 + tid] = c;
        const float sp = (nv > 0.0f) ? (nv + log1pf(expf(-nv)))
                                     : log1pf(expf(nv));
        g_std[t * 64 + tid] = sp + 0.01f;
    }
}

// ---------------------------------------------------------------------------
// (v0,i0) better-than ordering: value desc, index asc (jax top_k ties).
// Symmetric merge of two sorted top-2 pairs; both sides of a butterfly
// exchange compute the identical result (strict total order on (v, i)).
// ---------------------------------------------------------------------------
__device__ __forceinline__ void merge2(float& v0, int& i0, float& v1, int& i1,
                                       float ov0, int oi0, float ov1, int oi1)
{
    const bool fw = (v0 > ov0) || (v0 == ov0 && i0 < oi0);
    if (fw) {
        const bool w = (ov0 > v1) || (ov0 == v1 && oi0 < i1);
        if (w) { v1 = ov0; i1 = oi0; }
    } else {
        const bool w = (v0 > ov1) || (v0 == ov1 && i0 < oi1);
        v1 = w ? v0 : ov1;
        i1 = w ? i0 : oi1;
        v0 = ov0; i0 = oi0;
    }
}

// ---------------------------------------------------------------------------
// Kernel 2: per-token gating, 8 lanes per token.
// Lane j of an octet owns expert chunks j and j+8 (4 experts each), so every
// warp-wide LDG.128/STG.128 covers 4 tokens as FULL 128B lines (perfect
// coalescing -> minimal L1 wavefronts, DRAM-bound).
// ---------------------------------------------------------------------------
__global__ __launch_bounds__(256) void gate_kernel(
    const int*   __restrict__ taskID,
    const float* __restrict__ noise,
    float*       __restrict__ gates,
    float*       __restrict__ loadv,
    int B)
{
    __shared__ float s_cl[6 * 64];
    __shared__ float s_st[6 * 64];
    __shared__ float s_load[64];

    const int tid = threadIdx.x;
    if (tid < 64) s_load[tid] = 0.0f;
    for (int i = tid; i < 6 * 64; i += 256) {
        s_cl[i] = g_clean[i];
        s_st[i] = g_std[i];
    }
    __syncthreads();

    const int j   = tid & 7;            // lane within octet
    const int oct = tid >> 3;           // octet id in block (0..31)
    const long long base = (long long)blockIdx.x * 256 + oct;
    const int base0 = j * 4;            // experts of chunk j
    const int base1 = j * 4 + 32;       // experts of chunk j+8

    #pragma unroll 2
    for (int it = 0; it < 8; ++it) {
        const long long b = base + (long long)it * 32;
        const bool active = (b < (long long)B);
        const unsigned mask = __ballot_sync(0xffffffffu, active);
        if (!active) continue;

        const int t = __ldg(taskID + b);
        const float4* nz = (const float4*)(noise + (b << 6));
        const float4 n0 = nz[j];
        const float4 n1 = nz[j + 8];
        const float4* cl4 = (const float4*)(s_cl + t * 64);
        const float4* st4 = (const float4*)(s_st + t * 64);
        const float4 c0 = cl4[j], c1 = cl4[j + 8];
        const float4 s0 = st4[j], s1 = st4[j + 8];

        const float l0 = fmaf(n0.x, s0.x, c0.x);
        const float l1 = fmaf(n0.y, s0.y, c0.y);
        const float l2 = fmaf(n0.z, s0.z, c0.z);
        const float l3 = fmaf(n0.w, s0.w, c0.w);
        const float l4 = fmaf(n1.x, s1.x, c1.x);
        const float l5 = fmaf(n1.y, s1.y, c1.y);
        const float l6 = fmaf(n1.z, s1.z, c1.z);
        const float l7 = fmaf(n1.w, s1.w, c1.w);

        // local top-2 in increasing-index scan order (strict > keeps earliest)
        float v0 = l0, v1; int i0 = base0, i1;
        if (l1 > v0) { v1 = v0; i1 = i0; v0 = l1; i0 = base0 + 1; }
        else         { v1 = l1; i1 = base0 + 1; }
        if      (l2 > v0) { v1 = v0; i1 = i0; v0 = l2; i0 = base0 + 2; }
        else if (l2 > v1) { v1 = l2; i1 = base0 + 2; }
        if      (l3 > v0) { v1 = v0; i1 = i0; v0 = l3; i0 = base0 + 3; }
        else if (l3 > v1) { v1 = l3; i1 = base0 + 3; }
        if      (l4 > v0) { v1 = v0; i1 = i0; v0 = l4; i0 = base1 + 0; }
        else if (l4 > v1) { v1 = l4; i1 = base1 + 0; }
        if      (l5 > v0) { v1 = v0; i1 = i0; v0 = l5; i0 = base1 + 1; }
        else if (l5 > v1) { v1 = l5; i1 = base1 + 1; }
        if      (l6 > v0) { v1 = v0; i1 = i0; v0 = l6; i0 = base1 + 2; }
        else if (l6 > v1) { v1 = l6; i1 = base1 + 2; }
        if      (l7 > v0) { v1 = v0; i1 = i0; v0 = l7; i0 = base1 + 3; }
        else if (l7 > v1) { v1 = l7; i1 = base1 + 3; }

        // 3-step symmetric butterfly within the octet -> all 8 lanes get top-2
        #pragma unroll
        for (int d = 1; d < 8; d <<= 1) {
            const float ov0 = __shfl_xor_sync(mask, v0, d, 8);
            const int   oi0 = __shfl_xor_sync(mask, i0, d, 8);
            const float ov1 = __shfl_xor_sync(mask, v1, d, 8);
            const int   oi1 = __shfl_xor_sync(mask, i1, d, 8);
            merge2(v0, i0, v1, i1, ov0, oi0, ov1, oi1);
        }

        // softmax over the top-2 (v0 >= v1 -> stable)
        const float e  = __expf(v1 - v0);
        const float ga = 1.0f / (1.0f + e);
        const float gb = e * ga;

        float4 o0, o1;
        o0.x = (base0 + 0 == i0) ? ga : ((base0 + 0 == i1) ? gb : 0.0f);
        o0.y = (base0 + 1 == i0) ? ga : ((base0 + 1 == i1) ? gb : 0.0f);
        o0.z = (base0 + 2 == i0) ? ga : ((base0 + 2 == i1) ? gb : 0.0f);
        o0.w = (base0 + 3 == i0) ? ga : ((base0 + 3 == i1) ? gb : 0.0f);
        o1.x = (base1 + 0 == i0) ? ga : ((base1 + 0 == i1) ? gb : 0.0f);
        o1.y = (base1 + 1 == i0) ? ga : ((base1 + 1 == i1) ? gb : 0.0f);
        o1.z = (base1 + 2 == i0) ? ga : ((base1 + 2 == i1) ? gb : 0.0f);
        o1.w = (base1 + 3 == i0) ? ga : ((base1 + 3 == i1) ? gb : 0.0f);

        float4* og = (float4*)(gates + (b << 6));
        og[j]     = o0;
        og[j + 8] = o1;

        if (j == 0) {
            atomicAdd(&s_load[i0], ga);
            atomicAdd(&s_load[i1], gb);
        }
    }
    __syncthreads();
    if (tid < 64) atomicAdd(&loadv[tid], s_load[tid]);
}

// ---------------------------------------------------------------------------
// Launch
// ---------------------------------------------------------------------------
extern "C" void kernel_launch(void* const* d_in, const int* in_sizes, int n_in,
                              void* d_out, int out_size)
{
    const int*   taskID = (const int*)  d_in[0];
    const float* noise  = (const float*)d_in[1];
    const float* embed  = (const float*)d_in[2];
    const float* ekeys  = (const float*)d_in[3];
    const float* Wq     = (const float*)d_in[4];
    const float* bq     = (const float*)d_in[5];
    const float* Wk     = (const float*)d_in[6];
    const float* bk     = (const float*)d_in[7];
    const float* Wg     = (const float*)d_in[8];
    const float* bg     = (const float*)d_in[9];
    const float* Wn     = (const float*)d_in[10];
    const float* bn     = (const float*)d_in[11];

    const int B = in_sizes[0];
    float* gates = (float*)d_out;
    float* loadv = (float*)d_out + (out_size - 64);  // load tail

    precompute_kernel<<<6, 64>>>(embed, ekeys, Wq, bq, Wk, bk,
                                 Wg, bg, Wn, bn, loadv);

    const int blocks = (B + 255) / 256;
    gate_kernel<<<blocks, 256>>>(taskID, noise, gates, loadv, B);
}

// round 3
// speedup vs baseline: 1.5565x; 1.0934x over previous
#include <cuda_runtime.h>
#include <math.h>
#include <float.h>

// Per-task precomputed gating tables: only 6 distinct taskIDs exist.
__device__ float g_clean[6 * 64];
__device__ float g_std[6 * 64];

// ---------------------------------------------------------------------------
// Kernel 1: per-task precompute (6 blocks x 64 threads). Tiny.
// ---------------------------------------------------------------------------
__global__ void precompute_kernel(
    const float* __restrict__ embed,   // (6, 32)
    const float* __restrict__ ekeys,   // (32, 32)
    const float* __restrict__ Wq,      // (32, 32)
    const float* __restrict__ bq,      // (32)
    const float* __restrict__ Wk,      // (32, 32)
    const float* __restrict__ bk,      // (32)
    const float* __restrict__ Wg,      // (64, 32)
    const float* __restrict__ bg,      // (64)
    const float* __restrict__ Wn,      // (64, 32)
    const float* __restrict__ bn,      // (64)
    float* __restrict__ load_out)      // (64) -> zero it
{
    const int t = blockIdx.x;
    const int tid = threadIdx.x;

    __shared__ float s_q[32];
    __shared__ float s_k[32][32];   // [expert s][feature i]
    __shared__ float s_ew[32];

    if (t == 0 && tid < 64) load_out[tid] = 0.0f;

    // q = (embed[t] @ Wq^T + bq) * 1/sqrt(8)
    if (tid < 32) {
        float acc = bq[tid];
        #pragma unroll
        for (int j = 0; j < 32; j++)
            acc = fmaf(embed[t * 32 + j], Wq[tid * 32 + j], acc);
        s_q[tid] = acc * 0.35355339059327373f;
    }

    // k = expert_keys @ Wk^T + bk  (32x32 entries; 64 threads x 16 each)
    for (int p = tid; p < 1024; p += 64) {
        const int s = p >> 5, i = p & 31;
        float acc = bk[i];
        #pragma unroll
        for (int j = 0; j < 32; j++)
            acc = fmaf(ekeys[s * 32 + j], Wk[i * 32 + j], acc);
        s_k[s][i] = acc;
    }
    __syncthreads();

    // Warp 0 (lanes = experts s): scores, per-head softmax, mean, softmax.
    if (tid < 32) {
        float sc[4];
        #pragma unroll
        for (int h = 0; h < 4; h++) {
            float acc = 0.0f;
            #pragma unroll
            for (int d = 0; d < 8; d++)
                acc = fmaf(s_q[h * 8 + d], s_k[tid][h * 8 + d], acc);
            sc[h] = acc;
        }
        float aw = 0.0f;
        #pragma unroll
        for (int h = 0; h < 4; h++) {
            float m = sc[h];
            #pragma unroll
            for (int d = 16; d; d >>= 1)
                m = fmaxf(m, __shfl_xor_sync(0xffffffffu, m, d));
            float e = expf(sc[h] - m);
            float sum = e;
            #pragma unroll
            for (int d = 16; d; d >>= 1)
                sum += __shfl_xor_sync(0xffffffffu, sum, d);
            aw += 0.25f * (e / sum);
        }
        float m2 = aw;
        #pragma unroll
        for (int d = 16; d; d >>= 1)
            m2 = fmaxf(m2, __shfl_xor_sync(0xffffffffu, m2, d));
        float e2 = expf(aw - m2);
        float s2 = e2;
        #pragma unroll
        for (int d = 16; d; d >>= 1)
            s2 += __shfl_xor_sync(0xffffffffu, s2, d);
        s_ew[tid] = e2 / s2;
    }
    __syncthreads();

    // clean_logits[e], noise_std[e]; one thread per expert e = tid (0..63)
    {
        float c = bg[tid];
        float nv = bn[tid];
        #pragma unroll
        for (int s = 0; s < 32; s++) {
            const float w = s_ew[s];
            c  = fmaf(w, Wg[tid * 32 + s], c);
            nv = fmaf(w, Wn[tid * 32 + s], nv);
        }
        g_clean[t * 64 + tid] = c;
        const float sp = (nv > 0.0f) ? (nv + log1pf(expf(-nv)))
                                     : log1pf(expf(nv));
        g_std[t * 64 + tid] = sp + 0.01f;
    }
}

// ---------------------------------------------------------------------------
// Branchless top-2 update: value desc, scan order keeps earliest index on ties
// (strict > matches jax.lax.top_k).
// ---------------------------------------------------------------------------
__device__ __forceinline__ void upd2(float l, int gi,
                                     float& v0, int& i0, float& v1, int& i1)
{
    const bool p0 = l > v0;
    const bool p1 = l > v1;
    const float nv1 = p0 ? v0 : (p1 ? l : v1);
    const int   ni1 = p0 ? i0 : (p1 ? gi : i1);
    v0 = p0 ? l : v0;
    i0 = p0 ? gi : i0;
    v1 = nv1;
    i1 = ni1;
}

// ---------------------------------------------------------------------------
// Branchless symmetric merge of two sorted top-2 pairs under the total order
// (value desc, index asc). Both sides of a butterfly compute identical output.
// ---------------------------------------------------------------------------
__device__ __forceinline__ void merge2(float& v0, int& i0, float& v1, int& i1,
                                       float ov0, int oi0, float ov1, int oi1)
{
    const bool fw = (v0 > ov0) || (v0 == ov0 && i0 < oi0);
    const float w0  = fw ? v0  : ov0;   // overall winner
    const int   w0i = fw ? i0  : oi0;
    const float c   = fw ? ov0 : v0;    // loser's top (candidate for 2nd)
    const int   ci  = fw ? oi0 : i0;
    const float b   = fw ? v1  : ov1;   // winner's own second
    const int   bi  = fw ? i1  : oi1;
    const bool  w   = (c > b) || (c == b && ci < bi);
    v0 = w0;  i0 = w0i;
    v1 = w ? c  : b;
    i1 = w ? ci : bi;
}

// ---------------------------------------------------------------------------
// Kernel 2: per-token gating, 8 lanes per token (perfect 128B-line coalescing).
// Gates row written as zero quads + <=2 predicated scalar patch stores by the
// lane that owns the quad (same-thread program order => patch lands last).
// ---------------------------------------------------------------------------
__global__ __launch_bounds__(256) void gate_kernel(
    const int*   __restrict__ taskID,
    const float* __restrict__ noise,
    float*       __restrict__ gates,
    float*       __restrict__ loadv,
    int B)
{
    __shared__ float s_cl[6 * 64];
    __shared__ float s_st[6 * 64];
    __shared__ float s_load[64];

    const int tid = threadIdx.x;
    if (tid < 64) s_load[tid] = 0.0f;
    for (int i = tid; i < 6 * 64; i += 256) {
        s_cl[i] = g_clean[i];
        s_st[i] = g_std[i];
    }
    __syncthreads();

    const int j   = tid & 7;            // lane within octet
    const int oct = tid >> 3;           // octet id in block (0..31)
    const long long base = (long long)blockIdx.x * 256 + oct;
    const int base0 = j * 4;            // experts of chunk j
    const int base1 = j * 4 + 32;       // experts of chunk j+8

    const float4 z4 = make_float4(0.0f, 0.0f, 0.0f, 0.0f);

    #pragma unroll
    for (int it = 0; it < 8; ++it) {
        const long long b = base + (long long)it * 32;
        const bool active = (b < (long long)B);
        const unsigned mask = __ballot_sync(0xffffffffu, active);
        if (!active) continue;

        const int t = __ldg(taskID + b);
        const float4* nz = (const float4*)(noise + (b << 6));
        float* grow = gates + (b << 6);
        float4* og = (float4*)grow;

        const float4 n0 = nz[j];
        const float4 n1 = nz[j + 8];

        // Zero the two quads this lane owns, up front (patched below).
        og[j]     = z4;
        og[j + 8] = z4;

        const float4* cl4 = (const float4*)(s_cl + t * 64);
        const float4* st4 = (const float4*)(s_st + t * 64);
        const float4 c0 = cl4[j], c1 = cl4[j + 8];
        const float4 s0 = st4[j], s1 = st4[j + 8];

        const float l0 = fmaf(n0.x, s0.x, c0.x);
        const float l1 = fmaf(n0.y, s0.y, c0.y);
        const float l2 = fmaf(n0.z, s0.z, c0.z);
        const float l3 = fmaf(n0.w, s0.w, c0.w);
        const float l4 = fmaf(n1.x, s1.x, c1.x);
        const float l5 = fmaf(n1.y, s1.y, c1.y);
        const float l6 = fmaf(n1.z, s1.z, c1.z);
        const float l7 = fmaf(n1.w, s1.w, c1.w);

        // local top-2, branchless, scan order = increasing global index
        float v0 = l0, v1 = -FLT_MAX;
        int i0 = base0, i1 = base0;
        upd2(l1, base0 + 1, v0, i0, v1, i1);
        upd2(l2, base0 + 2, v0, i0, v1, i1);
        upd2(l3, base0 + 3, v0, i0, v1, i1);
        upd2(l4, base1 + 0, v0, i0, v1, i1);
        upd2(l5, base1 + 1, v0, i0, v1, i1);
        upd2(l6, base1 + 2, v0, i0, v1, i1);
        upd2(l7, base1 + 3, v0, i0, v1, i1);

        // 3-step symmetric butterfly within the octet
        #pragma unroll
        for (int d = 1; d < 8; d <<= 1) {
            const float ov0 = __shfl_xor_sync(mask, v0, d, 8);
            const int   oi0 = __shfl_xor_sync(mask, i0, d, 8);
            const float ov1 = __shfl_xor_sync(mask, v1, d, 8);
            const int   oi1 = __shfl_xor_sync(mask, i1, d, 8);
            merge2(v0, i0, v1, i1, ov0, oi0, ov1, oi1);
        }

        // softmax over the top-2 (v0 >= v1 -> stable)
        const float e  = __expf(v1 - v0);
        const float ga = __fdividef(1.0f, 1.0f + e);
        const float gb = e * ga;

        // patch stores: owner lane of quad (i>>2) is ((i>>2)&7) == j, and it
        // is exactly the lane that wrote that zero quad above.
        if (((i0 >> 2) & 7) == j) grow[i0] = ga;
        if (((i1 >> 2) & 7) == j) grow[i1] = gb;

        if (j == 0) {
            atomicAdd(&s_load[i0], ga);
            atomicAdd(&s_load[i1], gb);
        }
    }
    __syncthreads();
    if (tid < 64) atomicAdd(&loadv[tid], s_load[tid]);
}

// ---------------------------------------------------------------------------
// Launch
// ---------------------------------------------------------------------------
extern "C" void kernel_launch(void* const* d_in, const int* in_sizes, int n_in,
                              void* d_out, int out_size)
{
    const int*   taskID = (const int*)  d_in[0];
    const float* noise  = (const float*)d_in[1];
    const float* embed  = (const float*)d_in[2];
    const float* ekeys  = (const float*)d_in[3];
    const float* Wq     = (const float*)d_in[4];
    const float* bq     = (const float*)d_in[5];
    const float* Wk     = (const float*)d_in[6];
    const float* bk     = (const float*)d_in[7];
    const float* Wg     = (const float*)d_in[8];
    const float* bg     = (const float*)d_in[9];
    const float* Wn     = (const float*)d_in[10];
    const float* bn     = (const float*)d_in[11];

    const int B = in_sizes[0];
    float* gates = (float*)d_out;
    float* loadv = (float*)d_out + (out_size - 64);  // load tail

    precompute_kernel<<<6, 64>>>(embed, ekeys, Wq, bq, Wk, bk,
                                 Wg, bg, Wn, bn, loadv);

    const int blocks = (B + 255) / 256;
    gate_kernel<<<blocks, 256>>>(taskID, noise, gates, loadv, B);
}

// round 4
// speedup vs baseline: 1.6449x; 1.0568x over previous
#include <cuda_runtime.h>
#include <math.h>
#include <float.h>

// Per-task precomputed gating tables: only 6 distinct taskIDs exist.
__device__ float g_clean[6 * 64];
__device__ float g_std[6 * 64];

// ---------------------------------------------------------------------------
// Kernel 1: per-task precompute (6 blocks x 256 threads). All weights staged
// in shared via coalesced float4 loads.
// ---------------------------------------------------------------------------
__global__ __launch_bounds__(256) void precompute_kernel(
    const float* __restrict__ embed,   // (6, 32)
    const float* __restrict__ ekeys,   // (32, 32)
    const float* __restrict__ Wq,      // (32, 32)
    const float* __restrict__ bq,      // (32)
    const float* __restrict__ Wk,      // (32, 32)
    const float* __restrict__ bk,      // (32)
    const float* __restrict__ Wg,      // (64, 32)
    const float* __restrict__ bg,      // (64)
    const float* __restrict__ Wn,      // (64, 32)
    const float* __restrict__ bn,      // (64)
    float* __restrict__ load_out)      // (64) -> zero it
{
    const int t = blockIdx.x;
    const int tid = threadIdx.x;

    __shared__ float s_wq[1024], s_wk[1024], s_ek[1024];
    __shared__ float s_wg[2048], s_wn[2048];
    __shared__ float s_q[32];
    __shared__ float s_k[32][32];
    __shared__ float s_ew[32];

    if (t == 0 && tid < 64) load_out[tid] = 0.0f;

    // Stage weights (coalesced float4)
    ((float4*)s_wq)[tid] = ((const float4*)Wq)[tid];
    ((float4*)s_wk)[tid] = ((const float4*)Wk)[tid];
    ((float4*)s_ek)[tid] = ((const float4*)ekeys)[tid];
    ((float4*)s_wg)[tid]       = ((const float4*)Wg)[tid];
    ((float4*)s_wg)[tid + 256] = ((const float4*)Wg)[tid + 256];
    ((float4*)s_wn)[tid]       = ((const float4*)Wn)[tid];
    ((float4*)s_wn)[tid + 256] = ((const float4*)Wn)[tid + 256];
    __syncthreads();

    // q = (embed[t] @ Wq^T + bq) * 1/sqrt(8)
    if (tid < 32) {
        float acc = bq[tid];
        #pragma unroll
        for (int jj = 0; jj < 32; jj++)
            acc = fmaf(embed[t * 32 + jj], s_wq[tid * 32 + jj], acc);
        s_q[tid] = acc * 0.35355339059327373f;
    }

    // k = expert_keys @ Wk^T + bk  (1024 entries; 256 threads x 4)
    {
        const int p0 = tid * 4;
        const int s = p0 >> 5;
        #pragma unroll
        for (int q = 0; q < 4; q++) {
            const int i = (p0 + q) & 31;
            float acc = bk[i];
            #pragma unroll
            for (int jj = 0; jj < 32; jj++)
                acc = fmaf(s_ek[s * 32 + jj], s_wk[i * 32 + jj], acc);
            s_k[s][i] = acc;
        }
    }
    __syncthreads();

    // Warp 0 (lanes = experts s): scores, per-head softmax, mean, softmax.
    if (tid < 32) {
        float sc[4];
        #pragma unroll
        for (int h = 0; h < 4; h++) {
            float acc = 0.0f;
            #pragma unroll
            for (int d = 0; d < 8; d++)
                acc = fmaf(s_q[h * 8 + d], s_k[tid][h * 8 + d], acc);
            sc[h] = acc;
        }
        float aw = 0.0f;
        #pragma unroll
        for (int h = 0; h < 4; h++) {
            float m = sc[h];
            #pragma unroll
            for (int d = 16; d; d >>= 1)
                m = fmaxf(m, __shfl_xor_sync(0xffffffffu, m, d));
            float e = expf(sc[h] - m);
            float sum = e;
            #pragma unroll
            for (int d = 16; d; d >>= 1)
                sum += __shfl_xor_sync(0xffffffffu, sum, d);
            aw += 0.25f * (e / sum);
        }
        float m2 = aw;
        #pragma unroll
        for (int d = 16; d; d >>= 1)
            m2 = fmaxf(m2, __shfl_xor_sync(0xffffffffu, m2, d));
        float e2 = expf(aw - m2);
        float s2 = e2;
        #pragma unroll
        for (int d = 16; d; d >>= 1)
            s2 += __shfl_xor_sync(0xffffffffu, s2, d);
        s_ew[tid] = e2 / s2;
    }
    __syncthreads();

    // clean_logits[e], noise_std[e]; threads 0..63
    if (tid < 64) {
        float c = bg[tid];
        float nv = bn[tid];
        #pragma unroll
        for (int s = 0; s < 32; s++) {
            const float w = s_ew[s];
            c  = fmaf(w, s_wg[tid * 32 + s], c);
            nv = fmaf(w, s_wn[tid * 32 + s], nv);
        }
        g_clean[t * 64 + tid] = c;
        const float sp = (nv > 0.0f) ? (nv + log1pf(expf(-nv)))
                                     : log1pf(expf(nv));
        g_std[t * 64 + tid] = sp + 0.01f;
    }
}

// ---------------------------------------------------------------------------
// Order-preserving float <-> u32 key maps (monotone; exact).
// ---------------------------------------------------------------------------
__device__ __forceinline__ unsigned f2ord(float f) {
    const unsigned b = __float_as_uint(f);
    return b ^ (((unsigned)((int)b >> 31)) | 0x80000000u);
}
__device__ __forceinline__ float ord2f(unsigned u) {
    const unsigned b = u ^ ((~(unsigned)((int)u >> 31)) | 0x80000000u);
    return __uint_as_float(b);
}

// Branchless top-2 update on u32 keys; strict > keeps earliest index (jax).
__device__ __forceinline__ void upd2u(unsigned u, int gi,
                                      unsigned& u0, int& i0,
                                      unsigned& u1, int& i1)
{
    const bool p0 = u > u0;
    const bool p1 = u > u1;
    const unsigned nu1 = p0 ? u0 : (p1 ? u : u1);
    const int      ni1 = p0 ? i0 : (p1 ? gi : i1);
    u0 = p0 ? u : u0;
    i0 = p0 ? gi : i0;
    u1 = nu1;
    i1 = ni1;
}

// ---------------------------------------------------------------------------
// Kernel 2: per-token gating, 8 lanes per token, REDUX-based exact top-2.
// ---------------------------------------------------------------------------
__global__ __launch_bounds__(256) void gate_kernel(
    const int*   __restrict__ taskID,
    const float* __restrict__ noise,
    float*       __restrict__ gates,
    float*       __restrict__ loadv,
    int B)
{
    __shared__ float s_cl[6 * 64];
    __shared__ float s_st[6 * 64];
    __shared__ float s_load[64];

    const int tid = threadIdx.x;
    if (tid < 64) s_load[tid] = 0.0f;
    for (int i = tid; i < 6 * 64; i += 256) {
        s_cl[i] = g_clean[i];
        s_st[i] = g_std[i];
    }
    __syncthreads();

    const int j = tid & 7;                           // lane within octet
    const unsigned m8 = 0xFFu << (((tid >> 3) & 3) * 8);  // octet mask in warp
    const long long base = (long long)blockIdx.x * 256 + (tid >> 3);
    const int base0 = j * 4;
    const int base1 = j * 4 + 32;
    const float4 z4 = make_float4(0.0f, 0.0f, 0.0f, 0.0f);

    // Per-token body (token index b, task t, noise quads n0/n1 preloaded).
    auto process = [&](long long b, int t, float4 n0, float4 n1) {
        float* grow = gates + (b << 6);
        float4* og = (float4*)grow;
        __stcs(og + j, z4);
        __stcs(og + j + 8, z4);

        const float4* cl4 = (const float4*)(s_cl + t * 64);
        const float4* st4 = (const float4*)(s_st + t * 64);
        const float4 c0 = cl4[j], c1 = cl4[j + 8];
        const float4 s0 = st4[j], s1 = st4[j + 8];

        const unsigned k0 = f2ord(fmaf(n0.x, s0.x, c0.x));
        const unsigned k1 = f2ord(fmaf(n0.y, s0.y, c0.y));
        const unsigned k2 = f2ord(fmaf(n0.z, s0.z, c0.z));
        const unsigned k3 = f2ord(fmaf(n0.w, s0.w, c0.w));
        const unsigned k4 = f2ord(fmaf(n1.x, s1.x, c1.x));
        const unsigned k5 = f2ord(fmaf(n1.y, s1.y, c1.y));
        const unsigned k6 = f2ord(fmaf(n1.z, s1.z, c1.z));
        const unsigned k7 = f2ord(fmaf(n1.w, s1.w, c1.w));

        // local top-2 (scan order = increasing global index)
        unsigned u0 = k0, u1 = 0u;
        int i0 = base0, i1 = base0;
        upd2u(k1, base0 + 1, u0, i0, u1, i1);
        upd2u(k2, base0 + 2, u0, i0, u1, i1);
        upd2u(k3, base0 + 3, u0, i0, u1, i1);
        upd2u(k4, base1 + 0, u0, i0, u1, i1);
        upd2u(k5, base1 + 1, u0, i0, u1, i1);
        upd2u(k6, base1 + 2, u0, i0, u1, i1);
        upd2u(k7, base1 + 3, u0, i0, u1, i1);

        // Global top-1: max key, then min index among owners of that key.
        const unsigned g1 = __reduce_max_sync(m8, u0);
        const unsigned c1i = (u0 == g1) ? (unsigned)i0 : 0xFFFFu;
        const int gi1 = (int)__reduce_min_sync(m8, c1i);

        // Global top-2: exclude the chosen element, max again, min index.
        const unsigned cu2 = (i0 == gi1) ? u1 : u0;
        const unsigned g2 = __reduce_max_sync(m8, cu2);
        const unsigned c2i = (u0 == g2 && i0 != gi1) ? (unsigned)i0
                           : ((u1 == g2 && i1 != gi1) ? (unsigned)i1 : 0xFFFFu);
        const int gi2 = (int)__reduce_min_sync(m8, c2i);

        // softmax over the top-2 (v0 >= v1 -> stable)
        const float v0 = ord2f(g1);
        const float v1 = ord2f(g2);
        const float e  = __expf(v1 - v0);
        const float ga = __fdividef(1.0f, 1.0f + e);
        const float gb = e * ga;

        // Patch stores: lane ((i>>2)&7)==j owns the quad it zeroed above;
        // same-thread program order => patch lands after the zero.
        if (((gi1 >> 2) & 7) == j) grow[gi1] = ga;
        if (((gi2 >> 2) & 7) == j) grow[gi2] = gb;

        if (j == 0) {
            atomicAdd(&s_load[gi1], ga);
            atomicAdd(&s_load[gi2], gb);
        }
    };

    if ((base | 224) < (long long)B &&
        ((long long)blockIdx.x + 1) * 256 <= (long long)B) {
        // Full block: unguarded, depth-1 software pipeline.
        long long b = base;
        int t = __ldg(taskID + b);
        float4 n0 = __ldcs((const float4*)(noise + (b << 6)) + j);
        float4 n1 = __ldcs((const float4*)(noise + (b << 6)) + j + 8);
        #pragma unroll
        for (int it = 0; it < 8; ++it) {
            long long bn = b + 32;
            int tn = 0; float4 p0 = z4, p1 = z4;
            if (it < 7) {
                tn = __ldg(taskID + bn);
                p0 = __ldcs((const float4*)(noise + (bn << 6)) + j);
                p1 = __ldcs((const float4*)(noise + (bn << 6)) + j + 8);
            }
            process(b, t, n0, n1);
            b = bn; t = tn; n0 = p0; n1 = p1;
        }
    } else {
        // Tail block: guarded (condition uniform within each octet).
        for (int it = 0; it < 8; ++it) {
            const long long b = base + (long long)it * 32;
            if (b < (long long)B) {
                const int t = __ldg(taskID + b);
                const float4 n0 = __ldcs((const float4*)(noise + (b << 6)) + j);
                const float4 n1 = __ldcs((const float4*)(noise + (b << 6)) + j + 8);
                process(b, t, n0, n1);
            }
        }
    }

    __syncthreads();
    if (tid < 64) atomicAdd(&loadv[tid], s_load[tid]);
}

// ---------------------------------------------------------------------------
// Launch
// ---------------------------------------------------------------------------
extern "C" void kernel_launch(void* const* d_in, const int* in_sizes, int n_in,
                              void* d_out, int out_size)
{
    const int*   taskID = (const int*)  d_in[0];
    const float* noise  = (const float*)d_in[1];
    const float* embed  = (const float*)d_in[2];
    const float* ekeys  = (const float*)d_in[3];
    const float* Wq     = (const float*)d_in[4];
    const float* bq     = (const float*)d_in[5];
    const float* Wk     = (const float*)d_in[6];
    const float* bk     = (const float*)d_in[7];
    const float* Wg     = (const float*)d_in[8];
    const float* bg     = (const float*)d_in[9];
    const float* Wn     = (const float*)d_in[10];
    const float* bn     = (const float*)d_in[11];

    const int B = in_sizes[0];
    float* gates = (float*)d_out;
    float* loadv = (float*)d_out + (out_size - 64);  // load tail

    precompute_kernel<<<6, 256>>>(embed, ekeys, Wq, bq, Wk, bk,
                                  Wg, bg, Wn, bn, loadv);

    const int blocks = (B + 255) / 256;
    gate_kernel<<<blocks, 256>>>(taskID, noise, gates, loadv, B);
}

// round 5
// speedup vs baseline: 1.9040x; 1.1575x over previous
#include <cuda_runtime.h>
#include <math.h>
#include <float.h>

// Per-task precomputed gating tables: only 6 distinct taskIDs exist.
__device__ float g_clean[6 * 64];
__device__ float g_std[6 * 64];

// ---------------------------------------------------------------------------
// Kernel 1: per-task precompute (6 blocks x 256 threads). All weights staged
// in shared via coalesced float4 loads.
// ---------------------------------------------------------------------------
__global__ __launch_bounds__(256) void precompute_kernel(
    const float* __restrict__ embed,   // (6, 32)
    const float* __restrict__ ekeys,   // (32, 32)
    const float* __restrict__ Wq,      // (32, 32)
    const float* __restrict__ bq,      // (32)
    const float* __restrict__ Wk,      // (32, 32)
    const float* __restrict__ bk,      // (32)
    const float* __restrict__ Wg,      // (64, 32)
    const float* __restrict__ bg,      // (64)
    const float* __restrict__ Wn,      // (64, 32)
    const float* __restrict__ bn,      // (64)
    float* __restrict__ load_out)      // (64) -> zero it
{
    const int t = blockIdx.x;
    const int tid = threadIdx.x;

    __shared__ float s_wq[1024], s_wk[1024], s_ek[1024];
    __shared__ float s_wg[2048], s_wn[2048];
    __shared__ float s_q[32];
    __shared__ float s_k[32][32];
    __shared__ float s_ew[32];

    if (t == 0 && tid < 64) load_out[tid] = 0.0f;

    // Stage weights (coalesced float4)
    ((float4*)s_wq)[tid] = ((const float4*)Wq)[tid];
    ((float4*)s_wk)[tid] = ((const float4*)Wk)[tid];
    ((float4*)s_ek)[tid] = ((const float4*)ekeys)[tid];
    ((float4*)s_wg)[tid]       = ((const float4*)Wg)[tid];
    ((float4*)s_wg)[tid + 256] = ((const float4*)Wg)[tid + 256];
    ((float4*)s_wn)[tid]       = ((const float4*)Wn)[tid];
    ((float4*)s_wn)[tid + 256] = ((const float4*)Wn)[tid + 256];
    __syncthreads();

    // q = (embed[t] @ Wq^T + bq) * 1/sqrt(8)
    if (tid < 32) {
        float acc = bq[tid];
        #pragma unroll
        for (int jj = 0; jj < 32; jj++)
            acc = fmaf(embed[t * 32 + jj], s_wq[tid * 32 + jj], acc);
        s_q[tid] = acc * 0.35355339059327373f;
    }

    // k = expert_keys @ Wk^T + bk  (1024 entries; 256 threads x 4)
    {
        const int p0 = tid * 4;
        const int s = p0 >> 5;
        #pragma unroll
        for (int q = 0; q < 4; q++) {
            const int i = (p0 + q) & 31;
            float acc = bk[i];
            #pragma unroll
            for (int jj = 0; jj < 32; jj++)
                acc = fmaf(s_ek[s * 32 + jj], s_wk[i * 32 + jj], acc);
            s_k[s][i] = acc;
        }
    }
    __syncthreads();

    // Warp 0 (lanes = experts s): scores, per-head softmax, mean, softmax.
    if (tid < 32) {
        float sc[4];
        #pragma unroll
        for (int h = 0; h < 4; h++) {
            float acc = 0.0f;
            #pragma unroll
            for (int d = 0; d < 8; d++)
                acc = fmaf(s_q[h * 8 + d], s_k[tid][h * 8 + d], acc);
            sc[h] = acc;
        }
        float aw = 0.0f;
        #pragma unroll
        for (int h = 0; h < 4; h++) {
            float m = sc[h];
            #pragma unroll
            for (int d = 16; d; d >>= 1)
                m = fmaxf(m, __shfl_xor_sync(0xffffffffu, m, d));
            float e = expf(sc[h] - m);
            float sum = e;
            #pragma unroll
            for (int d = 16; d; d >>= 1)
                sum += __shfl_xor_sync(0xffffffffu, sum, d);
            aw += 0.25f * (e / sum);
        }
        float m2 = aw;
        #pragma unroll
        for (int d = 16; d; d >>= 1)
            m2 = fmaxf(m2, __shfl_xor_sync(0xffffffffu, m2, d));
        float e2 = expf(aw - m2);
        float s2 = e2;
        #pragma unroll
        for (int d = 16; d; d >>= 1)
            s2 += __shfl_xor_sync(0xffffffffu, s2, d);
        s_ew[tid] = e2 / s2;
    }
    __syncthreads();

    // clean_logits[e], noise_std[e]; threads 0..63
    if (tid < 64) {
        float c = bg[tid];
        float nv = bn[tid];
        #pragma unroll
        for (int s = 0; s < 32; s++) {
            const float w = s_ew[s];
            c  = fmaf(w, s_wg[tid * 32 + s], c);
            nv = fmaf(w, s_wn[tid * 32 + s], nv);
        }
        g_clean[t * 64 + tid] = c;
        const float sp = (nv > 0.0f) ? (nv + log1pf(expf(-nv)))
                                     : log1pf(expf(nv));
        g_std[t * 64 + tid] = sp + 0.01f;
    }
}

// ---------------------------------------------------------------------------
// Branchless top-2 update: value desc, scan order keeps earliest index on ties
// (strict > matches jax.lax.top_k).
// ---------------------------------------------------------------------------
__device__ __forceinline__ void upd2(float l, int gi,
                                     float& v0, int& i0, float& v1, int& i1)
{
    const bool p0 = l > v0;
    const bool p1 = l > v1;
    const float nv1 = p0 ? v0 : (p1 ? l : v1);
    const int   ni1 = p0 ? i0 : (p1 ? gi : i1);
    v0 = p0 ? l : v0;
    i0 = p0 ? gi : i0;
    v1 = nv1;
    i1 = ni1;
}

// ---------------------------------------------------------------------------
// Branchless symmetric merge of two sorted top-2 pairs under the total order
// (value desc, index asc). Both sides of a butterfly compute identical output.
// ---------------------------------------------------------------------------
__device__ __forceinline__ void merge2(float& v0, int& i0, float& v1, int& i1,
                                       float ov0, int oi0, float ov1, int oi1)
{
    const bool fw = (v0 > ov0) || (v0 == ov0 && i0 < oi0);
    const float w0  = fw ? v0  : ov0;   // overall winner
    const int   w0i = fw ? i0  : oi0;
    const float c   = fw ? ov0 : v0;    // loser's top (candidate for 2nd)
    const int   ci  = fw ? oi0 : i0;
    const float b   = fw ? v1  : ov1;   // winner's own second
    const int   bi  = fw ? i1  : oi1;
    const bool  w   = (c > b) || (c == b && ci < bi);
    v0 = w0;  i0 = w0i;
    v1 = w ? c  : b;
    i1 = w ? ci : bi;
}

// ---------------------------------------------------------------------------
// Kernel 2: per-token gating, 8 lanes per token (perfect 128B coalescing).
// Incremental pointers across the 8 iterations; no per-iteration 64-bit
// index math; unguarded fast path for full blocks.
// ---------------------------------------------------------------------------
__global__ __launch_bounds__(256) void gate_kernel(
    const int*   __restrict__ taskID,
    const float* __restrict__ noise,
    float*       __restrict__ gates,
    float*       __restrict__ loadv,
    int B)
{
    __shared__ float s_cl[6 * 64];
    __shared__ float s_st[6 * 64];
    __shared__ float s_load[64];

    const int tid = threadIdx.x;
    if (tid < 64) s_load[tid] = 0.0f;
    for (int i = tid; i < 6 * 64; i += 256) {
        s_cl[i] = g_clean[i];
        s_st[i] = g_std[i];
    }
    __syncthreads();

    const int j = tid & 7;              // lane within octet
    const int base0 = j * 4;            // experts of chunk j
    const int base1 = j * 4 + 32;       // experts of chunk j+8
    const float4 z4 = make_float4(0.0f, 0.0f, 0.0f, 0.0f);

    const int tok0 = blockIdx.x * 256 + (tid >> 3);   // first token (fits int)
    // Row pointers computed once; advanced by constants per iteration.
    const float4* nq = (const float4*)(noise + (size_t)tok0 * 64) + j;
    float4*       gq = (float4*)      (gates + (size_t)tok0 * 64) + j;
    const int*    tp = taskID + tok0;

    // Per-token body. nq/gq point at this token's chunk j; t = task id.
    auto process = [&](const float4* nqi, float4* gqi, int t,
                       unsigned mask) {
        gqi[0] = z4;
        gqi[8] = z4;
        const float4 n0 = nqi[0];
        const float4 n1 = nqi[8];

        const float4* cl4 = (const float4*)(s_cl + t * 64);
        const float4* st4 = (const float4*)(s_st + t * 64);
        const float4 c0 = cl4[j], c1 = cl4[j + 8];
        const float4 s0 = st4[j], s1 = st4[j + 8];

        const float l0 = fmaf(n0.x, s0.x, c0.x);
        const float l1 = fmaf(n0.y, s0.y, c0.y);
        const float l2 = fmaf(n0.z, s0.z, c0.z);
        const float l3 = fmaf(n0.w, s0.w, c0.w);
        const float l4 = fmaf(n1.x, s1.x, c1.x);
        const float l5 = fmaf(n1.y, s1.y, c1.y);
        const float l6 = fmaf(n1.z, s1.z, c1.z);
        const float l7 = fmaf(n1.w, s1.w, c1.w);

        // local top-2, branchless, scan order = increasing global index
        float v0 = l0, v1 = -FLT_MAX;
        int i0 = base0, i1 = base0;
        upd2(l1, base0 + 1, v0, i0, v1, i1);
        upd2(l2, base0 + 2, v0, i0, v1, i1);
        upd2(l3, base0 + 3, v0, i0, v1, i1);
        upd2(l4, base1 + 0, v0, i0, v1, i1);
        upd2(l5, base1 + 1, v0, i0, v1, i1);
        upd2(l6, base1 + 2, v0, i0, v1, i1);
        upd2(l7, base1 + 3, v0, i0, v1, i1);

        // 3-step symmetric butterfly within the octet
        #pragma unroll
        for (int d = 1; d < 8; d <<= 1) {
            const float ov0 = __shfl_xor_sync(mask, v0, d, 8);
            const int   oi0 = __shfl_xor_sync(mask, i0, d, 8);
            const float ov1 = __shfl_xor_sync(mask, v1, d, 8);
            const int   oi1 = __shfl_xor_sync(mask, i1, d, 8);
            merge2(v0, i0, v1, i1, ov0, oi0, ov1, oi1);
        }

        // softmax over the top-2 (v0 >= v1 -> stable)
        const float e  = __expf(v1 - v0);
        const float ga = __fdividef(1.0f, 1.0f + e);
        const float gb = e * ga;

        // Patch stores: lane ((i>>2)&7)==j owns the quad it zeroed above;
        // same-thread program order => patch lands after the zero.
        float* grow = (float*)(gqi - j);
        if (((i0 >> 2) & 7) == j) grow[i0] = ga;
        if (((i1 >> 2) & 7) == j) grow[i1] = gb;

        if (j == 0) {
            atomicAdd(&s_load[i0], ga);
            atomicAdd(&s_load[i1], gb);
        }
    };

    if ((blockIdx.x + 1) * 256 <= (unsigned)B) {
        // Full block: unguarded, pointer-increment loop.
        #pragma unroll
        for (int it = 0; it < 8; ++it) {
            const int t = __ldg(tp);
            process(nq, gq, t, 0xffffffffu);
            nq += 512;          // 32 tokens * 16 float4
            gq += 512;
            tp += 32;
        }
    } else {
        // Tail block: guarded (condition uniform within each octet).
        int tok = tok0;
        for (int it = 0; it < 8; ++it) {
            const bool active = tok < B;
            const unsigned mask = __ballot_sync(0xffffffffu, active);
            if (active) {
                const int t = __ldg(tp);
                process(nq, gq, t, mask);
            }
            nq += 512;
            gq += 512;
            tp += 32;
            tok += 32;
        }
    }

    __syncthreads();
    if (tid < 64) atomicAdd(&loadv[tid], s_load[tid]);
}

// ---------------------------------------------------------------------------
// Launch
// ---------------------------------------------------------------------------
extern "C" void kernel_launch(void* const* d_in, const int* in_sizes, int n_in,
                              void* d_out, int out_size)
{
    const int*   taskID = (const int*)  d_in[0];
    const float* noise  = (const float*)d_in[1];
    const float* embed  = (const float*)d_in[2];
    const float* ekeys  = (const float*)d_in[3];
    const float* Wq     = (const float*)d_in[4];
    const float* bq     = (const float*)d_in[5];
    const float* Wk     = (const float*)d_in[6];
    const float* bk     = (const float*)d_in[7];
    const float* Wg     = (const float*)d_in[8];
    const float* bg     = (const float*)d_in[9];
    const float* Wn     = (const float*)d_in[10];
    const float* bn     = (const float*)d_in[11];

    const int B = in_sizes[0];
    float* gates = (float*)d_out;
    float* loadv = (float*)d_out + (out_size - 64);  // load tail

    precompute_kernel<<<6, 256>>>(embed, ekeys, Wq, bq, Wk, bk,
                                  Wg, bg, Wn, bn, loadv);

    const int blocks = (B + 255) / 256;
    gate_kernel<<<blocks, 256>>>(taskID, noise, gates, loadv, B);
}